// round 1
// baseline (speedup 1.0000x reference)
#include <cuda_runtime.h>
#include <math.h>
#include <stddef.h>

#define NN 6000
#define NP 6016          // padded rows (multiple of 64)
#define EE 192000
#define H  128
#define NEG_BIG (-3.0e38f)

// ---------------- static device scratch (no allocs allowed) ----------------
__device__ float g_dinv[NN];
__device__ int   g_cnt[NN];
__device__ int   g_ptr[NN + 1];
__device__ int   g_cursor[NN];
__device__ int   g_src[EE + NN];
__device__ float g_nrm[EE + NN];
__device__ float g_hw[NP * H];
__device__ float g_ha[NP * H];
__device__ float g_hb[NP * H];
__device__ float g_xr[NP * H];
__device__ float g_xg[NP * H];
__device__ float g_q[4 * NP * H];
__device__ float g_k[4 * NP * H];
__device__ float g_hcat[(size_t)NN * 640];

// ---------------- graph preprocessing ----------------
__global__ void k_init_cnt(int* cnt) {
    int i = blockIdx.x * blockDim.x + threadIdx.x;
    if (i < NN) cnt[i] = 1;  // self loop
}

__global__ void k_count(const int* __restrict__ edges, int* cnt) {
    int e = blockIdx.x * blockDim.x + threadIdx.x;
    if (e < EE) atomicAdd(&cnt[edges[EE + e]], 1);  // col = edges[1]
}

__global__ void k_dinv(const int* __restrict__ cnt, float* dinv) {
    int i = blockIdx.x * blockDim.x + threadIdx.x;
    if (i < NN) dinv[i] = rsqrtf((float)cnt[i]);
}

// single-CTA exclusive scan of cnt -> ptr[NN+1]; also seeds cursor
__global__ void k_scan(const int* __restrict__ cnt, int* ptr, int* cursor) {
    __shared__ int part[1024];
    int t = threadIdx.x;
    int base = t * 6;
    int v[6];
    int s = 0;
#pragma unroll
    for (int j = 0; j < 6; j++) {
        int idx = base + j;
        v[j] = (idx < NN) ? cnt[idx] : 0;
        s += v[j];
    }
    part[t] = s;
    __syncthreads();
    for (int off = 1; off < 1024; off <<= 1) {
        int x = 0;
        if (t >= off) x = part[t - off];
        __syncthreads();
        part[t] += x;
        __syncthreads();
    }
    int run = part[t] - s;  // exclusive
#pragma unroll
    for (int j = 0; j < 6; j++) {
        int idx = base + j;
        if (idx <= NN) ptr[idx] = run;
        if (idx < NN) cursor[idx] = run;
        run += v[j];
    }
}

__global__ void k_fill(const int* __restrict__ edges, const float* __restrict__ dinv,
                       int* cursor, int* src, float* nrm) {
    int e = blockIdx.x * blockDim.x + threadIdx.x;
    if (e >= EE + NN) return;
    int s, t;
    if (e < EE) { s = edges[e]; t = edges[EE + e]; }
    else { s = t = e - EE; }
    float w = dinv[s] * dinv[t];
    int p = atomicAdd(&cursor[t], 1);
    src[p] = s;
    nrm[p] = w;
}

// ---------------- GCN kernels ----------------
// first layer: x (N,3) @ W0 (3,128)
__global__ void k_lin3(const float* __restrict__ x, const float* __restrict__ W0,
                       float* __restrict__ out) {
    int node = blockIdx.x * 2 + (threadIdx.x >> 7);
    int c = threadIdx.x & 127;
    if (node >= NN) return;
    float x0 = x[node * 3 + 0], x1 = x[node * 3 + 1], x2 = x[node * 3 + 2];
    out[node * H + c] = x0 * W0[c] + x1 * W0[H + c] + x2 * W0[2 * H + c];
}

// out[n] = relu(bias + sum_p nrm[p]*hw[src[p]])   (warp per node, float4 per lane)
__global__ void k_gather(const float* __restrict__ hw, const int* __restrict__ ptr,
                         const int* __restrict__ src, const float* __restrict__ nrm,
                         const float* __restrict__ bias, float* __restrict__ out) {
    int node = (blockIdx.x * blockDim.x + threadIdx.x) >> 5;
    int lane = threadIdx.x & 31;
    if (node >= NN) return;
    const float4* hw4 = (const float4*)hw;
    float4 acc = make_float4(0.f, 0.f, 0.f, 0.f);
    int p0 = ptr[node], p1 = ptr[node + 1];
#pragma unroll 4
    for (int p = p0; p < p1; p++) {
        int s = __ldg(&src[p]);
        float w = __ldg(&nrm[p]);
        float4 h = hw4[(size_t)s * 32 + lane];
        acc.x += w * h.x; acc.y += w * h.y; acc.z += w * h.z; acc.w += w * h.w;
    }
    float4 b = ((const float4*)bias)[lane];
    float4 o;
    o.x = fmaxf(acc.x + b.x, 0.f);
    o.y = fmaxf(acc.y + b.y, 0.f);
    o.z = fmaxf(acc.z + b.z, 0.f);
    o.w = fmaxf(acc.w + b.w, 0.f);
    ((float4*)out)[(size_t)node * 32 + lane] = o;
}

// ---------------- generic SGEMM tile: C[M,128] = A[M,K]@B[K,128] (+bias)(relu) ----------------
__device__ __forceinline__ void gemm_tile(const float* __restrict__ A, const float* __restrict__ B,
                                          const float* __restrict__ bias, float* __restrict__ C,
                                          int M, int K, int lda, int ldc, int relu, int rowbase) {
    __shared__ __align__(16) float Ast[32 * 33];   // [kk][r]
    __shared__ __align__(16) float Bs[32 * 132];   // [kk][c] padded
    int tid = threadIdx.x;
    int tx = tid & 15, ty = tid >> 4;
    float acc[4][8];
#pragma unroll
    for (int i = 0; i < 4; i++)
#pragma unroll
        for (int u = 0; u < 8; u++) acc[i][u] = 0.f;

    for (int kb = 0; kb < K; kb += 32) {
        __syncthreads();
        // load A chunk 32x32 (transposed into Ast)
#pragma unroll
        for (int i = 0; i < 2; i++) {
            int idx = tid + 128 * i;
            int r = idx >> 3;
            int f = (idx & 7) << 2;
            int row = rowbase + r;
            float4 v = make_float4(0.f, 0.f, 0.f, 0.f);
            if (row < M) v = *(const float4*)(A + (size_t)row * lda + kb + f);
            Ast[(f + 0) * 33 + r] = v.x;
            Ast[(f + 1) * 33 + r] = v.y;
            Ast[(f + 2) * 33 + r] = v.z;
            Ast[(f + 3) * 33 + r] = v.w;
        }
        // load B chunk 32x128
#pragma unroll
        for (int i = 0; i < 8; i++) {
            int idx = tid + 128 * i;
            int kk = idx >> 5;
            int c4 = (idx & 31) << 2;
            *(float4*)(Bs + kk * 132 + c4) = *(const float4*)(B + (size_t)(kb + kk) * H + c4);
        }
        __syncthreads();
#pragma unroll 8
        for (int kk = 0; kk < 32; kk++) {
            float4 b0 = *(const float4*)(Bs + kk * 132 + tx * 4);
            float4 b1 = *(const float4*)(Bs + kk * 132 + 64 + tx * 4);
#pragma unroll
            for (int i = 0; i < 4; i++) {
                float a = Ast[kk * 33 + ty * 4 + i];
                acc[i][0] += a * b0.x; acc[i][1] += a * b0.y;
                acc[i][2] += a * b0.z; acc[i][3] += a * b0.w;
                acc[i][4] += a * b1.x; acc[i][5] += a * b1.y;
                acc[i][6] += a * b1.z; acc[i][7] += a * b1.w;
            }
        }
    }
#pragma unroll
    for (int i = 0; i < 4; i++) {
        int row = rowbase + ty * 4 + i;
        if (row >= M) continue;
        float o[8];
#pragma unroll
        for (int u = 0; u < 8; u++) o[u] = acc[i][u];
        if (bias) {
#pragma unroll
            for (int u = 0; u < 4; u++) { o[u] += bias[tx * 4 + u]; o[u + 4] += bias[64 + tx * 4 + u]; }
        }
        if (relu) {
#pragma unroll
            for (int u = 0; u < 8; u++) o[u] = fmaxf(o[u], 0.f);
        }
        *(float4*)(C + (size_t)row * ldc + tx * 4) = make_float4(o[0], o[1], o[2], o[3]);
        *(float4*)(C + (size_t)row * ldc + 64 + tx * 4) = make_float4(o[4], o[5], o[6], o[7]);
    }
}

__global__ void gemm128_kernel(const float* __restrict__ A, const float* __restrict__ B,
                               const float* __restrict__ bias, float* __restrict__ C,
                               int M, int K, int lda, int ldc, int relu) {
    gemm_tile(A, B, bias, C, M, K, lda, ldc, relu, blockIdx.x * 32);
}

// q/k projection for all heads: grid (188, 4 heads, 2 [q|k])
__global__ void qk_kernel(const float* __restrict__ xr, const float* __restrict__ xg,
                          const float* __restrict__ Wa, const float* __restrict__ ba,
                          float* __restrict__ q, float* __restrict__ k) {
    const float* A = blockIdx.z ? xg : xr;
    float* C = (blockIdx.z ? k : q) + (size_t)blockIdx.y * NP * H;
    gemm_tile(A, Wa + blockIdx.y * H * H, ba + blockIdx.y * H, C, NN, H, H, H, 0,
              blockIdx.x * 32);
}

// ---------------- flash attention (fp32), Bq=64, Bk=64, 128 threads ----------------
__global__ void __launch_bounds__(128, 2)
flash_kernel(const float* __restrict__ qbuf, const float* __restrict__ kbuf,
             const float* __restrict__ vbuf, float* __restrict__ hcat) {
    extern __shared__ __align__(16) float sm[];
    float* Qs = sm;                    // 64*132
    float* KVs = sm + 64 * 132;        // 64*132 (K, then reused for V)
    float* Ps = sm + 2 * 64 * 132;     // 64*68
    int tid = threadIdx.x;
    int tx = tid & 15, ty = tid >> 4;
    int qbase = blockIdx.x * 64;
    int head = blockIdx.y;
    const float* Q = qbuf + (size_t)head * NP * H;
    const float* K = kbuf + (size_t)head * NP * H;

    // load Q tile (64x128)
#pragma unroll
    for (int i = 0; i < 16; i++) {
        int idx = tid + 128 * i;
        int r = idx >> 5;
        int c4 = (idx & 31) << 2;
        *(float4*)(Qs + r * 132 + c4) = *(const float4*)(Q + (size_t)(qbase + r) * H + c4);
    }

    float O[8][8];
    float m[8], l[8];
#pragma unroll
    for (int i = 0; i < 8; i++) {
        m[i] = NEG_BIG; l[i] = 0.f;
#pragma unroll
        for (int u = 0; u < 8; u++) O[i][u] = 0.f;
    }

    const int ntiles = (NN + 63) / 64;  // 94
    for (int kt = 0; kt < ntiles; kt++) {
        int kbase = kt * 64;
        __syncthreads();  // prior O-update done reading KVs
        // load K tile
#pragma unroll
        for (int i = 0; i < 16; i++) {
            int idx = tid + 128 * i;
            int r = idx >> 5;
            int c4 = (idx & 31) << 2;
            *(float4*)(KVs + r * 132 + c4) = *(const float4*)(K + (size_t)(kbase + r) * H + c4);
        }
        __syncthreads();

        // S = Q K^T  (thread: rows ty*8..+7, cols tx+16j)
        float S[8][4];
#pragma unroll
        for (int i = 0; i < 8; i++)
#pragma unroll
            for (int j = 0; j < 4; j++) S[i][j] = 0.f;
#pragma unroll 2
        for (int kk = 0; kk < 128; kk += 4) {
            float4 k0 = *(const float4*)(KVs + (tx + 0) * 132 + kk);
            float4 k1 = *(const float4*)(KVs + (tx + 16) * 132 + kk);
            float4 k2 = *(const float4*)(KVs + (tx + 32) * 132 + kk);
            float4 k3 = *(const float4*)(KVs + (tx + 48) * 132 + kk);
#pragma unroll
            for (int i = 0; i < 8; i++) {
                float4 qv = *(const float4*)(Qs + (ty * 8 + i) * 132 + kk);
                S[i][0] += qv.x * k0.x; S[i][0] += qv.y * k0.y; S[i][0] += qv.z * k0.z; S[i][0] += qv.w * k0.w;
                S[i][1] += qv.x * k1.x; S[i][1] += qv.y * k1.y; S[i][1] += qv.z * k1.z; S[i][1] += qv.w * k1.w;
                S[i][2] += qv.x * k2.x; S[i][2] += qv.y * k2.y; S[i][2] += qv.z * k2.z; S[i][2] += qv.w * k2.w;
                S[i][3] += qv.x * k3.x; S[i][3] += qv.y * k3.y; S[i][3] += qv.z * k3.z; S[i][3] += qv.w * k3.w;
            }
        }
        // mask padded columns
#pragma unroll
        for (int j = 0; j < 4; j++) {
            if (kbase + tx + 16 * j >= NN) {
#pragma unroll
                for (int i = 0; i < 8; i++) S[i][j] = NEG_BIG;
            }
        }
        // online softmax + write P
#pragma unroll
        for (int i = 0; i < 8; i++) {
            float mt = fmaxf(fmaxf(S[i][0], S[i][1]), fmaxf(S[i][2], S[i][3]));
            mt = fmaxf(mt, __shfl_xor_sync(0xffffffffu, mt, 1));
            mt = fmaxf(mt, __shfl_xor_sync(0xffffffffu, mt, 2));
            mt = fmaxf(mt, __shfl_xor_sync(0xffffffffu, mt, 4));
            mt = fmaxf(mt, __shfl_xor_sync(0xffffffffu, mt, 8));
            float mn = fmaxf(m[i], mt);
            float al = __expf(m[i] - mn);
            float p0 = __expf(S[i][0] - mn);
            float p1 = __expf(S[i][1] - mn);
            float p2 = __expf(S[i][2] - mn);
            float p3 = __expf(S[i][3] - mn);
            float rs = (p0 + p1) + (p2 + p3);
            rs += __shfl_xor_sync(0xffffffffu, rs, 1);
            rs += __shfl_xor_sync(0xffffffffu, rs, 2);
            rs += __shfl_xor_sync(0xffffffffu, rs, 4);
            rs += __shfl_xor_sync(0xffffffffu, rs, 8);
            l[i] = l[i] * al + rs;
            m[i] = mn;
            Ps[(ty * 8 + i) * 68 + tx + 0] = p0;
            Ps[(ty * 8 + i) * 68 + tx + 16] = p1;
            Ps[(ty * 8 + i) * 68 + tx + 32] = p2;
            Ps[(ty * 8 + i) * 68 + tx + 48] = p3;
#pragma unroll
            for (int u = 0; u < 8; u++) O[i][u] *= al;
        }
        __syncthreads();  // P visible, K reads done
        // load V tile into same buffer
#pragma unroll
        for (int i = 0; i < 16; i++) {
            int idx = tid + 128 * i;
            int r = idx >> 5;
            int c4 = (idx & 31) << 2;
            *(float4*)(KVs + r * 132 + c4) = *(const float4*)(vbuf + (size_t)(kbase + r) * H + c4);
        }
        __syncthreads();
        // O += P @ V  (thread cols: tx*4..+3 and 64+tx*4..+3)
#pragma unroll 4
        for (int c = 0; c < 64; c++) {
            float4 v0 = *(const float4*)(KVs + c * 132 + tx * 4);
            float4 v1 = *(const float4*)(KVs + c * 132 + 64 + tx * 4);
#pragma unroll
            for (int i = 0; i < 8; i++) {
                float p = Ps[(ty * 8 + i) * 68 + c];
                O[i][0] += p * v0.x; O[i][1] += p * v0.y; O[i][2] += p * v0.z; O[i][3] += p * v0.w;
                O[i][4] += p * v1.x; O[i][5] += p * v1.y; O[i][6] += p * v1.z; O[i][7] += p * v1.w;
            }
        }
    }
    // store: hcat[:, 128 + head*128 + col]
#pragma unroll
    for (int i = 0; i < 8; i++) {
        int row = qbase + ty * 8 + i;
        if (row >= NN) continue;
        float inv = 1.f / l[i];
        float* dst = hcat + (size_t)row * 640 + 128 + head * 128;
        *(float4*)(dst + tx * 4) =
            make_float4(O[i][0] * inv, O[i][1] * inv, O[i][2] * inv, O[i][3] * inv);
        *(float4*)(dst + 64 + tx * 4) =
            make_float4(O[i][4] * inv, O[i][5] * inv, O[i][6] * inv, O[i][7] * inv);
    }
}

// copy xr into hcat[:, 0:128]
__global__ void k_copyxr(const float* __restrict__ xr, float* __restrict__ hcat) {
    int idx = blockIdx.x * blockDim.x + threadIdx.x;
    if (idx >= NN * 32) return;
    int row = idx >> 5;
    int c4 = idx & 31;
    *(float4*)(hcat + (size_t)row * 640 + c4 * 4) = ((const float4*)xr)[(size_t)row * 32 + c4];
}

// final projection 128 -> 3
__global__ void k_wout(const float* __restrict__ h, const float* __restrict__ Wout,
                       const float* __restrict__ bout, float* __restrict__ out) {
    int n = blockIdx.x * blockDim.x + threadIdx.x;
    if (n >= NN) return;
    float a0 = bout[0], a1 = bout[1], a2 = bout[2];
    const float4* h4 = (const float4*)(h + (size_t)n * H);
#pragma unroll 8
    for (int k4 = 0; k4 < 32; k4++) {
        float4 v = h4[k4];
        int k = k4 * 4;
        a0 += v.x * Wout[(k + 0) * 3 + 0] + v.y * Wout[(k + 1) * 3 + 0] +
              v.z * Wout[(k + 2) * 3 + 0] + v.w * Wout[(k + 3) * 3 + 0];
        a1 += v.x * Wout[(k + 0) * 3 + 1] + v.y * Wout[(k + 1) * 3 + 1] +
              v.z * Wout[(k + 2) * 3 + 1] + v.w * Wout[(k + 3) * 3 + 1];
        a2 += v.x * Wout[(k + 0) * 3 + 2] + v.y * Wout[(k + 1) * 3 + 2] +
              v.z * Wout[(k + 2) * 3 + 2] + v.w * Wout[(k + 3) * 3 + 2];
    }
    out[n * 3 + 0] = a0;
    out[n * 3 + 1] = a1;
    out[n * 3 + 2] = a2;
}

// ---------------- host side ----------------
static void gemm128(const float* A, const float* B, const float* bias, float* C,
                    int M, int K, int lda, int ldc, int relu) {
    gemm128_kernel<<<(M + 31) / 32, 128>>>(A, B, bias, C, M, K, lda, ldc, relu);
}

static void encode(const float* x, const int* edges, const float* W0, const float* b0,
                   const float* Ws, const float* bs, float* out,
                   int* cnt, float* dinv, int* ptr, int* cursor, int* src, float* nrm,
                   float* hw, float* ha, float* hb) {
    k_init_cnt<<<(NN + 255) / 256, 256>>>(cnt);
    k_count<<<(EE + 255) / 256, 256>>>(edges, cnt);
    k_dinv<<<(NN + 255) / 256, 256>>>(cnt, dinv);
    k_scan<<<1, 1024>>>(cnt, ptr, cursor);
    k_fill<<<(EE + NN + 255) / 256, 256>>>(edges, dinv, cursor, src, nrm);

    k_lin3<<<(NN + 1) / 2, 256>>>(x, W0, hw);
    k_gather<<<(NN * 32 + 255) / 256, 256>>>(hw, ptr, src, nrm, b0, ha);
    gemm128(ha, Ws, 0, hw, NN, H, H, H, 0);
    k_gather<<<(NN * 32 + 255) / 256, 256>>>(hw, ptr, src, nrm, bs, hb);
    gemm128(hb, Ws + H * H, 0, hw, NN, H, H, H, 0);
    k_gather<<<(NN * 32 + 255) / 256, 256>>>(hw, ptr, src, nrm, bs + H, out);
}

extern "C" void kernel_launch(void* const* d_in, const int* in_sizes, int n_in,
                              void* d_out, int out_size) {
    const float* x_resting = (const float*)d_in[0];
    const float* x_rigid   = (const float*)d_in[1];
    const int*   e_rest    = (const int*)d_in[2];
    const int*   e_rigid   = (const int*)d_in[3];
    const float* Wr0 = (const float*)d_in[4];
    const float* br0 = (const float*)d_in[5];
    const float* Wr  = (const float*)d_in[6];
    const float* br  = (const float*)d_in[7];
    const float* Wg0 = (const float*)d_in[8];
    const float* bg0 = (const float*)d_in[9];
    const float* Wg  = (const float*)d_in[10];
    const float* bg  = (const float*)d_in[11];
    const float* Wa  = (const float*)d_in[12];
    const float* ba  = (const float*)d_in[13];
    const float* Wd0 = (const float*)d_in[14];
    const float* bd0 = (const float*)d_in[15];
    const float* Wd  = (const float*)d_in[16];
    const float* bd  = (const float*)d_in[17];
    const float* Wout = (const float*)d_in[18];
    const float* bout = (const float*)d_in[19];
    float* out = (float*)d_out;

    // resolve scratch symbols
    void *p_cnt, *p_dinv, *p_ptr, *p_cur, *p_src, *p_nrm;
    void *p_hw, *p_ha, *p_hb, *p_xr, *p_xg, *p_q, *p_k, *p_hcat;
    cudaGetSymbolAddress(&p_cnt, g_cnt);
    cudaGetSymbolAddress(&p_dinv, g_dinv);
    cudaGetSymbolAddress(&p_ptr, g_ptr);
    cudaGetSymbolAddress(&p_cur, g_cursor);
    cudaGetSymbolAddress(&p_src, g_src);
    cudaGetSymbolAddress(&p_nrm, g_nrm);
    cudaGetSymbolAddress(&p_hw, g_hw);
    cudaGetSymbolAddress(&p_ha, g_ha);
    cudaGetSymbolAddress(&p_hb, g_hb);
    cudaGetSymbolAddress(&p_xr, g_xr);
    cudaGetSymbolAddress(&p_xg, g_xg);
    cudaGetSymbolAddress(&p_q, g_q);
    cudaGetSymbolAddress(&p_k, g_k);
    cudaGetSymbolAddress(&p_hcat, g_hcat);

    // zero padded tails (K and V buffers must be finite in pad rows)
    cudaMemsetAsync(p_xg, 0, (size_t)NP * H * sizeof(float));
    cudaMemsetAsync(p_k, 0, (size_t)4 * NP * H * sizeof(float));

    // encoders
    encode(x_resting, e_rest, Wr0, br0, Wr, br, (float*)p_xr,
           (int*)p_cnt, (float*)p_dinv, (int*)p_ptr, (int*)p_cur, (int*)p_src,
           (float*)p_nrm, (float*)p_hw, (float*)p_ha, (float*)p_hb);
    encode(x_rigid, e_rigid, Wg0, bg0, Wg, bg, (float*)p_xg,
           (int*)p_cnt, (float*)p_dinv, (int*)p_ptr, (int*)p_cur, (int*)p_src,
           (float*)p_nrm, (float*)p_hw, (float*)p_ha, (float*)p_hb);

    // q/k projections for all 4 heads
    {
        dim3 grid((NN + 31) / 32, 4, 2);
        qk_kernel<<<grid, 128>>>((const float*)p_xr, (const float*)p_xg, Wa, ba,
                                 (float*)p_q, (float*)p_k);
    }

    // flash attention -> hcat[:, 128:640]
    {
        int smem = (2 * 64 * 132 + 64 * 68) * (int)sizeof(float);  // 84992 B
        cudaFuncSetAttribute(flash_kernel, cudaFuncAttributeMaxDynamicSharedMemorySize, smem);
        dim3 grid((NN + 63) / 64, 4);
        flash_kernel<<<grid, 128, smem>>>((const float*)p_q, (const float*)p_k,
                                          (const float*)p_xg, (float*)p_hcat);
    }
    k_copyxr<<<(NN * 32 + 255) / 256, 256>>>((const float*)p_xr, (float*)p_hcat);

    // decoder
    gemm128((const float*)p_hcat, Wd0, bd0, (float*)p_ha, NN, 5 * H, 5 * H, H, 1);
    gemm128((const float*)p_ha, Wd, bd, (float*)p_hb, NN, H, H, H, 1);
    gemm128((const float*)p_hb, Wd + H * H, bd + H, (float*)p_hw, NN, H, H, H, 1);
    k_wout<<<(NN + 255) / 256, 256>>>((const float*)p_hw, Wout, bout, out);
}

// round 2
// speedup vs baseline: 2.1057x; 2.1057x over previous
#include <cuda_runtime.h>
#include <math.h>
#include <stddef.h>

#define NN 6000
#define NP 6016          // padded rows (multiple of 64)
#define EE 192000
#define H  128
#define NEG_BIG (-3.0e38f)

// ---------------- packed fp32x2 helpers (sm_103a dual-issue fp32) ----------------
__device__ __forceinline__ void ffma2(unsigned long long& d, unsigned long long a,
                                      unsigned long long b) {
    asm("fma.rn.f32x2 %0, %1, %2, %0;" : "+l"(d) : "l"(a), "l"(b));
}
__device__ __forceinline__ unsigned long long mul2(unsigned long long a, unsigned long long b) {
    unsigned long long d;
    asm("mul.rn.f32x2 %0, %1, %2;" : "=l"(d) : "l"(a), "l"(b));
    return d;
}
__device__ __forceinline__ unsigned long long packdup(float p) {
    unsigned long long r;
    asm("mov.b64 %0, {%1, %1};" : "=l"(r) : "f"(p));
    return r;
}
__device__ __forceinline__ float2 unpk(unsigned long long v) {
    float2 f;
    asm("mov.b64 {%0, %1}, %2;" : "=f"(f.x), "=f"(f.y) : "l"(v));
    return f;
}

// ---------------- static device scratch (no allocs allowed) ----------------
__device__ float g_dinv[NN];
__device__ int   g_cnt[NN];
__device__ int   g_ptr[NN + 1];
__device__ int   g_cursor[NN];
__device__ int   g_src[EE + NN];
__device__ float g_nrm[EE + NN];
__device__ float g_hw[NP * H];
__device__ float g_ha[NP * H];
__device__ float g_hb[NP * H];
__device__ float g_xr[NP * H];
__device__ float g_xg[NP * H];
__device__ float g_q[4 * NP * H];
__device__ float g_k[4 * NP * H];
__device__ float g_hcat[(size_t)NN * 640];

// ---------------- graph preprocessing ----------------
__global__ void k_init_cnt(int* cnt) {
    int i = blockIdx.x * blockDim.x + threadIdx.x;
    if (i < NN) cnt[i] = 1;  // self loop
}

__global__ void k_count(const int* __restrict__ edges, int* cnt) {
    int e = blockIdx.x * blockDim.x + threadIdx.x;
    if (e < EE) atomicAdd(&cnt[edges[EE + e]], 1);  // col = edges[1]
}

__global__ void k_dinv(const int* __restrict__ cnt, float* dinv) {
    int i = blockIdx.x * blockDim.x + threadIdx.x;
    if (i < NN) dinv[i] = rsqrtf((float)cnt[i]);
}

// single-CTA exclusive scan of cnt -> ptr[NN+1]; also seeds cursor
__global__ void k_scan(const int* __restrict__ cnt, int* ptr, int* cursor) {
    __shared__ int part[1024];
    int t = threadIdx.x;
    int base = t * 6;
    int v[6];
    int s = 0;
#pragma unroll
    for (int j = 0; j < 6; j++) {
        int idx = base + j;
        v[j] = (idx < NN) ? cnt[idx] : 0;
        s += v[j];
    }
    part[t] = s;
    __syncthreads();
    for (int off = 1; off < 1024; off <<= 1) {
        int x = 0;
        if (t >= off) x = part[t - off];
        __syncthreads();
        part[t] += x;
        __syncthreads();
    }
    int run = part[t] - s;  // exclusive
#pragma unroll
    for (int j = 0; j < 6; j++) {
        int idx = base + j;
        if (idx <= NN) ptr[idx] = run;
        if (idx < NN) cursor[idx] = run;
        run += v[j];
    }
}

__global__ void k_fill(const int* __restrict__ edges, const float* __restrict__ dinv,
                       int* cursor, int* src, float* nrm) {
    int e = blockIdx.x * blockDim.x + threadIdx.x;
    if (e >= EE + NN) return;
    int s, t;
    if (e < EE) { s = edges[e]; t = edges[EE + e]; }
    else { s = t = e - EE; }
    float w = dinv[s] * dinv[t];
    int p = atomicAdd(&cursor[t], 1);
    src[p] = s;
    nrm[p] = w;
}

// ---------------- GCN kernels ----------------
__global__ void k_lin3(const float* __restrict__ x, const float* __restrict__ W0,
                       float* __restrict__ out) {
    int node = blockIdx.x * 2 + (threadIdx.x >> 7);
    int c = threadIdx.x & 127;
    if (node >= NN) return;
    float x0 = x[node * 3 + 0], x1 = x[node * 3 + 1], x2 = x[node * 3 + 2];
    out[node * H + c] = x0 * W0[c] + x1 * W0[H + c] + x2 * W0[2 * H + c];
}

__global__ void k_gather(const float* __restrict__ hw, const int* __restrict__ ptr,
                         const int* __restrict__ src, const float* __restrict__ nrm,
                         const float* __restrict__ bias, float* __restrict__ out) {
    int node = (blockIdx.x * blockDim.x + threadIdx.x) >> 5;
    int lane = threadIdx.x & 31;
    if (node >= NN) return;
    const float4* hw4 = (const float4*)hw;
    float4 acc = make_float4(0.f, 0.f, 0.f, 0.f);
    int p0 = ptr[node], p1 = ptr[node + 1];
#pragma unroll 4
    for (int p = p0; p < p1; p++) {
        int s = __ldg(&src[p]);
        float w = __ldg(&nrm[p]);
        float4 h = hw4[(size_t)s * 32 + lane];
        acc.x += w * h.x; acc.y += w * h.y; acc.z += w * h.z; acc.w += w * h.w;
    }
    float4 b = ((const float4*)bias)[lane];
    float4 o;
    o.x = fmaxf(acc.x + b.x, 0.f);
    o.y = fmaxf(acc.y + b.y, 0.f);
    o.z = fmaxf(acc.z + b.z, 0.f);
    o.w = fmaxf(acc.w + b.w, 0.f);
    ((float4*)out)[(size_t)node * 32 + lane] = o;
}

// ---------------- generic SGEMM tile: C[M,128] = A[M,K]@B[K,128] (+bias)(relu) ----------------
__device__ __forceinline__ void gemm_tile(const float* __restrict__ A, const float* __restrict__ B,
                                          const float* __restrict__ bias, float* __restrict__ C,
                                          int M, int K, int lda, int ldc, int relu, int rowbase) {
    __shared__ __align__(16) float Ast[32 * 33];   // [kk][r]
    __shared__ __align__(16) float Bs[32 * 132];   // [kk][c] padded
    int tid = threadIdx.x;
    int tx = tid & 15, ty = tid >> 4;
    unsigned long long acc2[4][4];
#pragma unroll
    for (int i = 0; i < 4; i++)
#pragma unroll
        for (int u = 0; u < 4; u++) acc2[i][u] = 0ull;

    for (int kb = 0; kb < K; kb += 32) {
        __syncthreads();
#pragma unroll
        for (int i = 0; i < 2; i++) {
            int idx = tid + 128 * i;
            int r = idx >> 3;
            int f = (idx & 7) << 2;
            int row = rowbase + r;
            float4 v = make_float4(0.f, 0.f, 0.f, 0.f);
            if (row < M) v = *(const float4*)(A + (size_t)row * lda + kb + f);
            Ast[(f + 0) * 33 + r] = v.x;
            Ast[(f + 1) * 33 + r] = v.y;
            Ast[(f + 2) * 33 + r] = v.z;
            Ast[(f + 3) * 33 + r] = v.w;
        }
#pragma unroll
        for (int i = 0; i < 8; i++) {
            int idx = tid + 128 * i;
            int kk = idx >> 5;
            int c4 = (idx & 31) << 2;
            *(float4*)(Bs + kk * 132 + c4) = *(const float4*)(B + (size_t)(kb + kk) * H + c4);
        }
        __syncthreads();
#pragma unroll 8
        for (int kk = 0; kk < 32; kk++) {
            ulonglong2 b0 = *(const ulonglong2*)(Bs + kk * 132 + tx * 4);
            ulonglong2 b1 = *(const ulonglong2*)(Bs + kk * 132 + 64 + tx * 4);
#pragma unroll
            for (int i = 0; i < 4; i++) {
                unsigned long long a2 = packdup(Ast[kk * 33 + ty * 4 + i]);
                ffma2(acc2[i][0], a2, b0.x);
                ffma2(acc2[i][1], a2, b0.y);
                ffma2(acc2[i][2], a2, b1.x);
                ffma2(acc2[i][3], a2, b1.y);
            }
        }
    }
#pragma unroll
    for (int i = 0; i < 4; i++) {
        int row = rowbase + ty * 4 + i;
        if (row >= M) continue;
        float o[8];
#pragma unroll
        for (int u = 0; u < 4; u++) {
            float2 f = unpk(acc2[i][u]);
            o[u * 2 + 0] = f.x;
            o[u * 2 + 1] = f.y;
        }
        if (bias) {
#pragma unroll
            for (int u = 0; u < 4; u++) { o[u] += bias[tx * 4 + u]; o[u + 4] += bias[64 + tx * 4 + u]; }
        }
        if (relu) {
#pragma unroll
            for (int u = 0; u < 8; u++) o[u] = fmaxf(o[u], 0.f);
        }
        *(float4*)(C + (size_t)row * ldc + tx * 4) = make_float4(o[0], o[1], o[2], o[3]);
        *(float4*)(C + (size_t)row * ldc + 64 + tx * 4) = make_float4(o[4], o[5], o[6], o[7]);
    }
}

__global__ void gemm128_kernel(const float* __restrict__ A, const float* __restrict__ B,
                               const float* __restrict__ bias, float* __restrict__ C,
                               int M, int K, int lda, int ldc, int relu) {
    gemm_tile(A, B, bias, C, M, K, lda, ldc, relu, blockIdx.x * 32);
}

// q/k projection for all heads: grid (188, 4 heads, 2 [q|k])
__global__ void qk_kernel(const float* __restrict__ xr, const float* __restrict__ xg,
                          const float* __restrict__ Wa, const float* __restrict__ ba,
                          float* __restrict__ q, float* __restrict__ k) {
    const float* A = blockIdx.z ? xg : xr;
    float* C = (blockIdx.z ? k : q) + (size_t)blockIdx.y * NP * H;
    gemm_tile(A, Wa + blockIdx.y * H * H, ba + blockIdx.y * H, C, NN, H, H, H, 0,
              blockIdx.x * 32);
}

// ---------------- flash attention (fp32, packed f32x2), Bq=64, Bk=64, 128 threads ----------------
__global__ void __launch_bounds__(128, 2)
flash_kernel(const float* __restrict__ qbuf, const float* __restrict__ kbuf,
             const float* __restrict__ vbuf, float* __restrict__ hcat) {
    extern __shared__ __align__(16) float sm[];
    float* Qs = sm;                    // 64*132
    float* KVs = sm + 64 * 132;        // 64*132 (K, then reused for V)
    float* Ps = sm + 2 * 64 * 132;     // 64*68
    int tid = threadIdx.x;
    int tx = tid & 15, ty = tid >> 4;
    int qbase = blockIdx.x * 64;
    int head = blockIdx.y;
    const float* Q = qbuf + (size_t)head * NP * H;
    const float* K = kbuf + (size_t)head * NP * H;

    // load Q tile (64x128)
#pragma unroll
    for (int i = 0; i < 16; i++) {
        int idx = tid + 128 * i;
        int r = idx >> 5;
        int c4 = (idx & 31) << 2;
        *(float4*)(Qs + r * 132 + c4) = *(const float4*)(Q + (size_t)(qbase + r) * H + c4);
    }

    unsigned long long O2[8][4];       // 8 rows x 8 cols as 4 packed pairs
    float m[8], l[8];
#pragma unroll
    for (int i = 0; i < 8; i++) {
        m[i] = NEG_BIG; l[i] = 0.f;
#pragma unroll
        for (int u = 0; u < 4; u++) O2[i][u] = 0ull;
    }

    const int ntiles = (NN + 63) / 64;  // 94
    for (int kt = 0; kt < ntiles; kt++) {
        int kbase = kt * 64;
        __syncthreads();  // prior O-update done reading KVs
        // load K tile
#pragma unroll
        for (int i = 0; i < 16; i++) {
            int idx = tid + 128 * i;
            int r = idx >> 5;
            int c4 = (idx & 31) << 2;
            *(float4*)(KVs + r * 132 + c4) = *(const float4*)(K + (size_t)(kbase + r) * H + c4);
        }
        __syncthreads();

        // S = Q K^T, packed along k
        unsigned long long S2[8][4];
#pragma unroll
        for (int i = 0; i < 8; i++)
#pragma unroll
            for (int j = 0; j < 4; j++) S2[i][j] = 0ull;
#pragma unroll 2
        for (int kk = 0; kk < 128; kk += 4) {
            ulonglong2 k0 = *(const ulonglong2*)(KVs + (tx + 0) * 132 + kk);
            ulonglong2 k1 = *(const ulonglong2*)(KVs + (tx + 16) * 132 + kk);
            ulonglong2 k2 = *(const ulonglong2*)(KVs + (tx + 32) * 132 + kk);
            ulonglong2 k3 = *(const ulonglong2*)(KVs + (tx + 48) * 132 + kk);
#pragma unroll
            for (int i = 0; i < 8; i++) {
                ulonglong2 qv = *(const ulonglong2*)(Qs + (ty * 8 + i) * 132 + kk);
                ffma2(S2[i][0], qv.x, k0.x); ffma2(S2[i][0], qv.y, k0.y);
                ffma2(S2[i][1], qv.x, k1.x); ffma2(S2[i][1], qv.y, k1.y);
                ffma2(S2[i][2], qv.x, k2.x); ffma2(S2[i][2], qv.y, k2.y);
                ffma2(S2[i][3], qv.x, k3.x); ffma2(S2[i][3], qv.y, k3.y);
            }
        }
        // reduce pairs -> scalars, mask padded columns
        float S[8][4];
#pragma unroll
        for (int i = 0; i < 8; i++)
#pragma unroll
            for (int j = 0; j < 4; j++) {
                float2 f = unpk(S2[i][j]);
                S[i][j] = f.x + f.y;
            }
#pragma unroll
        for (int j = 0; j < 4; j++) {
            if (kbase + tx + 16 * j >= NN) {
#pragma unroll
                for (int i = 0; i < 8; i++) S[i][j] = NEG_BIG;
            }
        }
        // online softmax + write P
#pragma unroll
        for (int i = 0; i < 8; i++) {
            float mt = fmaxf(fmaxf(S[i][0], S[i][1]), fmaxf(S[i][2], S[i][3]));
            mt = fmaxf(mt, __shfl_xor_sync(0xffffffffu, mt, 1));
            mt = fmaxf(mt, __shfl_xor_sync(0xffffffffu, mt, 2));
            mt = fmaxf(mt, __shfl_xor_sync(0xffffffffu, mt, 4));
            mt = fmaxf(mt, __shfl_xor_sync(0xffffffffu, mt, 8));
            float mn = fmaxf(m[i], mt);
            float al = __expf(m[i] - mn);
            float p0 = __expf(S[i][0] - mn);
            float p1 = __expf(S[i][1] - mn);
            float p2 = __expf(S[i][2] - mn);
            float p3 = __expf(S[i][3] - mn);
            float rs = (p0 + p1) + (p2 + p3);
            rs += __shfl_xor_sync(0xffffffffu, rs, 1);
            rs += __shfl_xor_sync(0xffffffffu, rs, 2);
            rs += __shfl_xor_sync(0xffffffffu, rs, 4);
            rs += __shfl_xor_sync(0xffffffffu, rs, 8);
            l[i] = l[i] * al + rs;
            m[i] = mn;
            Ps[(ty * 8 + i) * 68 + tx + 0] = p0;
            Ps[(ty * 8 + i) * 68 + tx + 16] = p1;
            Ps[(ty * 8 + i) * 68 + tx + 32] = p2;
            Ps[(ty * 8 + i) * 68 + tx + 48] = p3;
            unsigned long long al2 = packdup(al);
#pragma unroll
            for (int u = 0; u < 4; u++) O2[i][u] = mul2(O2[i][u], al2);
        }
        __syncthreads();  // P visible, K reads done
        // load V tile into same buffer
#pragma unroll
        for (int i = 0; i < 16; i++) {
            int idx = tid + 128 * i;
            int r = idx >> 5;
            int c4 = (idx & 31) << 2;
            *(float4*)(KVs + r * 132 + c4) = *(const float4*)(vbuf + (size_t)(kbase + r) * H + c4);
        }
        __syncthreads();
        // O += P @ V  (packed output-col pairs, p broadcast via mov.b64)
#pragma unroll 4
        for (int c = 0; c < 64; c++) {
            ulonglong2 v0 = *(const ulonglong2*)(KVs + c * 132 + tx * 4);
            ulonglong2 v1 = *(const ulonglong2*)(KVs + c * 132 + 64 + tx * 4);
#pragma unroll
            for (int i = 0; i < 8; i++) {
                unsigned long long pp = packdup(Ps[(ty * 8 + i) * 68 + c]);
                ffma2(O2[i][0], pp, v0.x);
                ffma2(O2[i][1], pp, v0.y);
                ffma2(O2[i][2], pp, v1.x);
                ffma2(O2[i][3], pp, v1.y);
            }
        }
    }
    // store: hcat[:, 128 + head*128 + col]
#pragma unroll
    for (int i = 0; i < 8; i++) {
        int row = qbase + ty * 8 + i;
        if (row >= NN) continue;
        float inv = 1.f / l[i];
        float* dst = hcat + (size_t)row * 640 + 128 + head * 128;
        float2 a0 = unpk(O2[i][0]);
        float2 a1 = unpk(O2[i][1]);
        float2 a2 = unpk(O2[i][2]);
        float2 a3 = unpk(O2[i][3]);
        *(float4*)(dst + tx * 4) =
            make_float4(a0.x * inv, a0.y * inv, a1.x * inv, a1.y * inv);
        *(float4*)(dst + 64 + tx * 4) =
            make_float4(a2.x * inv, a2.y * inv, a3.x * inv, a3.y * inv);
    }
}

// copy xr into hcat[:, 0:128]
__global__ void k_copyxr(const float* __restrict__ xr, float* __restrict__ hcat) {
    int idx = blockIdx.x * blockDim.x + threadIdx.x;
    if (idx >= NN * 32) return;
    int row = idx >> 5;
    int c4 = idx & 31;
    *(float4*)(hcat + (size_t)row * 640 + c4 * 4) = ((const float4*)xr)[(size_t)row * 32 + c4];
}

// final projection 128 -> 3
__global__ void k_wout(const float* __restrict__ h, const float* __restrict__ Wout,
                       const float* __restrict__ bout, float* __restrict__ out) {
    int n = blockIdx.x * blockDim.x + threadIdx.x;
    if (n >= NN) return;
    float a0 = bout[0], a1 = bout[1], a2 = bout[2];
    const float4* h4 = (const float4*)(h + (size_t)n * H);
#pragma unroll 8
    for (int k4 = 0; k4 < 32; k4++) {
        float4 v = h4[k4];
        int k = k4 * 4;
        a0 += v.x * Wout[(k + 0) * 3 + 0] + v.y * Wout[(k + 1) * 3 + 0] +
              v.z * Wout[(k + 2) * 3 + 0] + v.w * Wout[(k + 3) * 3 + 0];
        a1 += v.x * Wout[(k + 0) * 3 + 1] + v.y * Wout[(k + 1) * 3 + 1] +
              v.z * Wout[(k + 2) * 3 + 1] + v.w * Wout[(k + 3) * 3 + 1];
        a2 += v.x * Wout[(k + 0) * 3 + 2] + v.y * Wout[(k + 1) * 3 + 2] +
              v.z * Wout[(k + 2) * 3 + 2] + v.w * Wout[(k + 3) * 3 + 2];
    }
    out[n * 3 + 0] = a0;
    out[n * 3 + 1] = a1;
    out[n * 3 + 2] = a2;
}

// ---------------- host side ----------------
static void gemm128(const float* A, const float* B, const float* bias, float* C,
                    int M, int K, int lda, int ldc, int relu) {
    gemm128_kernel<<<(M + 31) / 32, 128>>>(A, B, bias, C, M, K, lda, ldc, relu);
}

static void encode(const float* x, const int* edges, const float* W0, const float* b0,
                   const float* Ws, const float* bs, float* out,
                   int* cnt, float* dinv, int* ptr, int* cursor, int* src, float* nrm,
                   float* hw, float* ha, float* hb) {
    k_init_cnt<<<(NN + 255) / 256, 256>>>(cnt);
    k_count<<<(EE + 255) / 256, 256>>>(edges, cnt);
    k_dinv<<<(NN + 255) / 256, 256>>>(cnt, dinv);
    k_scan<<<1, 1024>>>(cnt, ptr, cursor);
    k_fill<<<(EE + NN + 255) / 256, 256>>>(edges, dinv, cursor, src, nrm);

    k_lin3<<<(NN + 1) / 2, 256>>>(x, W0, hw);
    k_gather<<<(NN * 32 + 255) / 256, 256>>>(hw, ptr, src, nrm, b0, ha);
    gemm128(ha, Ws, 0, hw, NN, H, H, H, 0);
    k_gather<<<(NN * 32 + 255) / 256, 256>>>(hw, ptr, src, nrm, bs, hb);
    gemm128(hb, Ws + H * H, 0, hw, NN, H, H, H, 0);
    k_gather<<<(NN * 32 + 255) / 256, 256>>>(hw, ptr, src, nrm, bs + H, out);
}

extern "C" void kernel_launch(void* const* d_in, const int* in_sizes, int n_in,
                              void* d_out, int out_size) {
    const float* x_resting = (const float*)d_in[0];
    const float* x_rigid   = (const float*)d_in[1];
    const int*   e_rest    = (const int*)d_in[2];
    const int*   e_rigid   = (const int*)d_in[3];
    const float* Wr0 = (const float*)d_in[4];
    const float* br0 = (const float*)d_in[5];
    const float* Wr  = (const float*)d_in[6];
    const float* br  = (const float*)d_in[7];
    const float* Wg0 = (const float*)d_in[8];
    const float* bg0 = (const float*)d_in[9];
    const float* Wg  = (const float*)d_in[10];
    const float* bg  = (const float*)d_in[11];
    const float* Wa  = (const float*)d_in[12];
    const float* ba  = (const float*)d_in[13];
    const float* Wd0 = (const float*)d_in[14];
    const float* bd0 = (const float*)d_in[15];
    const float* Wd  = (const float*)d_in[16];
    const float* bd  = (const float*)d_in[17];
    const float* Wout = (const float*)d_in[18];
    const float* bout = (const float*)d_in[19];
    float* out = (float*)d_out;

    // resolve scratch symbols
    void *p_cnt, *p_dinv, *p_ptr, *p_cur, *p_src, *p_nrm;
    void *p_hw, *p_ha, *p_hb, *p_xr, *p_xg, *p_q, *p_k, *p_hcat;
    cudaGetSymbolAddress(&p_cnt, g_cnt);
    cudaGetSymbolAddress(&p_dinv, g_dinv);
    cudaGetSymbolAddress(&p_ptr, g_ptr);
    cudaGetSymbolAddress(&p_cur, g_cursor);
    cudaGetSymbolAddress(&p_src, g_src);
    cudaGetSymbolAddress(&p_nrm, g_nrm);
    cudaGetSymbolAddress(&p_hw, g_hw);
    cudaGetSymbolAddress(&p_ha, g_ha);
    cudaGetSymbolAddress(&p_hb, g_hb);
    cudaGetSymbolAddress(&p_xr, g_xr);
    cudaGetSymbolAddress(&p_xg, g_xg);
    cudaGetSymbolAddress(&p_q, g_q);
    cudaGetSymbolAddress(&p_k, g_k);
    cudaGetSymbolAddress(&p_hcat, g_hcat);

    // zero padded tails (K and V buffers must be finite in pad rows)
    cudaMemsetAsync(p_xg, 0, (size_t)NP * H * sizeof(float));
    cudaMemsetAsync(p_k, 0, (size_t)4 * NP * H * sizeof(float));

    // encoders
    encode(x_resting, e_rest, Wr0, br0, Wr, br, (float*)p_xr,
           (int*)p_cnt, (float*)p_dinv, (int*)p_ptr, (int*)p_cur, (int*)p_src,
           (float*)p_nrm, (float*)p_hw, (float*)p_ha, (float*)p_hb);
    encode(x_rigid, e_rigid, Wg0, bg0, Wg, bg, (float*)p_xg,
           (int*)p_cnt, (float*)p_dinv, (int*)p_ptr, (int*)p_cur, (int*)p_src,
           (float*)p_nrm, (float*)p_hw, (float*)p_ha, (float*)p_hb);

    // q/k projections for all 4 heads
    {
        dim3 grid((NN + 31) / 32, 4, 2);
        qk_kernel<<<grid, 128>>>((const float*)p_xr, (const float*)p_xg, Wa, ba,
                                 (float*)p_q, (float*)p_k);
    }

    // flash attention -> hcat[:, 128:640]
    {
        int smem = (2 * 64 * 132 + 64 * 68) * (int)sizeof(float);  // 84992 B
        cudaFuncSetAttribute(flash_kernel, cudaFuncAttributeMaxDynamicSharedMemorySize, smem);
        dim3 grid((NN + 63) / 64, 4);
        flash_kernel<<<grid, 128, smem>>>((const float*)p_q, (const float*)p_k,
                                          (const float*)p_xg, (float*)p_hcat);
    }
    k_copyxr<<<(NN * 32 + 255) / 256, 256>>>((const float*)p_xr, (float*)p_hcat);

    // decoder
    gemm128((const float*)p_hcat, Wd0, bd0, (float*)p_ha, NN, 5 * H, 5 * H, H, 1);
    gemm128((const float*)p_ha, Wd, bd, (float*)p_hb, NN, H, H, H, 1);
    gemm128((const float*)p_hb, Wd + H * H, bd + H, (float*)p_hw, NN, H, H, H, 1);
    k_wout<<<(NN + 255) / 256, 256>>>((const float*)p_hw, Wout, bout, out);
}

// round 3
// speedup vs baseline: 2.5209x; 1.1972x over previous
#include <cuda_runtime.h>
#include <math.h>
#include <stddef.h>

#define NN 6000
#define NP 6016          // padded rows (multiple of 64)
#define EE 192000
#define H  128
#define NEG_BIG (-3.0e38f)

// ---------------- packed fp32x2 helpers (sm_103a dual fp32) ----------------
__device__ __forceinline__ void ffma2(unsigned long long& d, unsigned long long a,
                                      unsigned long long b) {
    asm("fma.rn.f32x2 %0, %1, %2, %0;" : "+l"(d) : "l"(a), "l"(b));
}
__device__ __forceinline__ unsigned long long mul2(unsigned long long a, unsigned long long b) {
    unsigned long long d;
    asm("mul.rn.f32x2 %0, %1, %2;" : "=l"(d) : "l"(a), "l"(b));
    return d;
}
__device__ __forceinline__ unsigned long long packdup(float p) {
    unsigned long long r;
    asm("mov.b64 %0, {%1, %1};" : "=l"(r) : "f"(p));
    return r;
}
__device__ __forceinline__ float2 unpk(unsigned long long v) {
    float2 f;
    asm("mov.b64 {%0, %1}, %2;" : "=f"(f.x), "=f"(f.y) : "l"(v));
    return f;
}

// ---------------- static device scratch ----------------
__device__ float g_dinv[2 * NN];
__device__ int   g_cnt[2 * NN];
__device__ int   g_ptr[2 * (NN + 1)];
__device__ int   g_cursor[2 * NN];
__device__ int   g_src[2 * (EE + NN)];
__device__ float g_nrm[2 * (EE + NN)];
__device__ float g_hw[2 * NP * H];
__device__ float g_ha[2 * NP * H];
__device__ float g_xr[NP * H];
__device__ float g_xg[NP * H];
__device__ float g_q[4 * NP * H];
__device__ float g_k[4 * NP * H];
__device__ float g_hcat[(size_t)NN * 640];
__device__ float g_opart[(size_t)2 * 4 * NP * H];   // split-K partial O
__device__ float g_mpart[2 * 4 * NP];
__device__ float g_lpart[2 * 4 * NP];

// ---------------- graph preprocessing (batched over 2 graphs) ----------------
__global__ void k_count_b(const int* __restrict__ e0, const int* __restrict__ e1, int* cnt) {
    int e = blockIdx.x * blockDim.x + threadIdx.x;
    const int* ed = blockIdx.y ? e1 : e0;
    int* c = cnt + blockIdx.y * NN;
    if (e < EE) atomicAdd(&c[ed[EE + e]], 1);
}

// one CTA per graph: deg = cnt+1, dinv = rsqrt(deg), exclusive scan -> ptr, cursor
__global__ void k_scan_b(const int* __restrict__ cnt, int* ptr, int* cursor, float* dinv) {
    int g = blockIdx.x;
    const int* c = cnt + g * NN;
    int* P = ptr + g * (NN + 1);
    int* cur = cursor + g * NN;
    float* dv = dinv + g * NN;
    __shared__ int wsum[32];
    int t = threadIdx.x, lane = t & 31, wid = t >> 5;
    int base = t * 6;
    int v[6], s = 0;
#pragma unroll
    for (int j = 0; j < 6; j++) {
        int idx = base + j;
        int d = (idx < NN) ? (c[idx] + 1) : 0;
        v[j] = d; s += d;
        if (idx < NN) dv[idx] = rsqrtf((float)d);
    }
    int inc = s;
#pragma unroll
    for (int off = 1; off < 32; off <<= 1) {
        int x = __shfl_up_sync(0xffffffffu, inc, off);
        if (lane >= off) inc += x;
    }
    if (lane == 31) wsum[wid] = inc;
    __syncthreads();
    if (wid == 0) {
        int w = wsum[lane];
        int wi = w;
#pragma unroll
        for (int off = 1; off < 32; off <<= 1) {
            int x = __shfl_up_sync(0xffffffffu, wi, off);
            if (lane >= off) wi += x;
        }
        wsum[lane] = wi - w;  // exclusive warp base
    }
    __syncthreads();
    int run = wsum[wid] + (inc - s);  // thread-exclusive
#pragma unroll
    for (int j = 0; j < 6; j++) {
        int idx = base + j;
        if (idx <= NN) P[idx] = run;
        if (idx < NN) cur[idx] = run;
        run += v[j];
    }
}

__global__ void k_fill_b(const int* __restrict__ e0, const int* __restrict__ e1,
                         const float* __restrict__ dinv, int* cursor, int* src, float* nrm) {
    int g = blockIdx.y;
    int e = blockIdx.x * blockDim.x + threadIdx.x;
    if (e >= EE + NN) return;
    const int* ed = g ? e1 : e0;
    const float* dv = dinv + g * NN;
    int* cur = cursor + g * NN;
    int* sr = src + g * (EE + NN);
    float* nr = nrm + g * (EE + NN);
    int s, t;
    if (e < EE) { s = ed[e]; t = ed[EE + e]; }
    else { s = t = e - EE; }
    float w = dv[s] * dv[t];
    int p = atomicAdd(&cur[t], 1);
    sr[p] = s;
    nr[p] = w;
}

// ---------------- GCN kernels (batched) ----------------
__global__ void k_lin3_b(const float* __restrict__ x0, const float* __restrict__ x1,
                         const float* __restrict__ Wr0, const float* __restrict__ Wg0,
                         float* __restrict__ hw) {
    int g = blockIdx.y;
    const float* x = g ? x1 : x0;
    const float* W0 = g ? Wg0 : Wr0;
    float* out = hw + (size_t)g * NP * H;
    int node = blockIdx.x * 2 + (threadIdx.x >> 7);
    int c = threadIdx.x & 127;
    if (node >= NN) return;
    float a0 = x[node * 3 + 0], a1 = x[node * 3 + 1], a2 = x[node * 3 + 2];
    out[node * H + c] = a0 * W0[c] + a1 * W0[H + c] + a2 * W0[2 * H + c];
}

// out = relu(bias + sum nrm*hw[src]); batched; optional split outputs (final layer)
__global__ void k_gather_b(const float* __restrict__ hw, const int* __restrict__ ptr,
                           const int* __restrict__ src, const float* __restrict__ nrm,
                           const float* __restrict__ bias0, const float* __restrict__ bias1,
                           float* __restrict__ out0, float* __restrict__ out1,
                           float* __restrict__ hcat) {
    int g = blockIdx.y;
    int node = (blockIdx.x * blockDim.x + threadIdx.x) >> 5;
    int lane = threadIdx.x & 31;
    if (node >= NN) return;
    const float4* hw4 = (const float4*)(hw + (size_t)g * NP * H);
    const int* P = ptr + g * (NN + 1);
    const int* sr = src + g * (EE + NN);
    const float* nr = nrm + g * (EE + NN);
    const float* bias = g ? bias1 : bias0;
    float4 acc = make_float4(0.f, 0.f, 0.f, 0.f);
    int p0 = P[node], p1 = P[node + 1];
#pragma unroll 4
    for (int p = p0; p < p1; p++) {
        int s = __ldg(&sr[p]);
        float w = __ldg(&nr[p]);
        float4 h = hw4[(size_t)s * 32 + lane];
        acc.x += w * h.x; acc.y += w * h.y; acc.z += w * h.z; acc.w += w * h.w;
    }
    float4 b = ((const float4*)bias)[lane];
    float4 o;
    o.x = fmaxf(acc.x + b.x, 0.f);
    o.y = fmaxf(acc.y + b.y, 0.f);
    o.z = fmaxf(acc.z + b.z, 0.f);
    o.w = fmaxf(acc.w + b.w, 0.f);
    float* out = g ? out1 : out0;
    ((float4*)out)[(size_t)node * 32 + lane] = o;
    if (hcat && g == 0)
        *(float4*)(hcat + (size_t)node * 640 + lane * 4) = o;
}

// ---------------- generic SGEMM tile: C[M,128] = A[M,K]@B[K,128] (+bias)(relu) ----------------
__device__ __forceinline__ void gemm_tile(const float* __restrict__ A, const float* __restrict__ B,
                                          const float* __restrict__ bias, float* __restrict__ C,
                                          int M, int K, int lda, int ldc, int relu, int rowbase) {
    __shared__ __align__(16) float Ast[32 * 33];
    __shared__ __align__(16) float Bs[32 * 132];
    int tid = threadIdx.x;
    int tx = tid & 15, ty = tid >> 4;
    unsigned long long acc2[4][4];
#pragma unroll
    for (int i = 0; i < 4; i++)
#pragma unroll
        for (int u = 0; u < 4; u++) acc2[i][u] = 0ull;

    for (int kb = 0; kb < K; kb += 32) {
        __syncthreads();
#pragma unroll
        for (int i = 0; i < 2; i++) {
            int idx = tid + 128 * i;
            int r = idx >> 3;
            int f = (idx & 7) << 2;
            int row = rowbase + r;
            float4 v = make_float4(0.f, 0.f, 0.f, 0.f);
            if (row < M) v = *(const float4*)(A + (size_t)row * lda + kb + f);
            Ast[(f + 0) * 33 + r] = v.x;
            Ast[(f + 1) * 33 + r] = v.y;
            Ast[(f + 2) * 33 + r] = v.z;
            Ast[(f + 3) * 33 + r] = v.w;
        }
#pragma unroll
        for (int i = 0; i < 8; i++) {
            int idx = tid + 128 * i;
            int kk = idx >> 5;
            int c4 = (idx & 31) << 2;
            *(float4*)(Bs + kk * 132 + c4) = *(const float4*)(B + (size_t)(kb + kk) * H + c4);
        }
        __syncthreads();
#pragma unroll 8
        for (int kk = 0; kk < 32; kk++) {
            ulonglong2 b0 = *(const ulonglong2*)(Bs + kk * 132 + tx * 4);
            ulonglong2 b1 = *(const ulonglong2*)(Bs + kk * 132 + 64 + tx * 4);
#pragma unroll
            for (int i = 0; i < 4; i++) {
                unsigned long long a2 = packdup(Ast[kk * 33 + ty * 4 + i]);
                ffma2(acc2[i][0], a2, b0.x);
                ffma2(acc2[i][1], a2, b0.y);
                ffma2(acc2[i][2], a2, b1.x);
                ffma2(acc2[i][3], a2, b1.y);
            }
        }
    }
#pragma unroll
    for (int i = 0; i < 4; i++) {
        int row = rowbase + ty * 4 + i;
        if (row >= M) continue;
        float o[8];
#pragma unroll
        for (int u = 0; u < 4; u++) {
            float2 f = unpk(acc2[i][u]);
            o[u * 2 + 0] = f.x;
            o[u * 2 + 1] = f.y;
        }
        if (bias) {
#pragma unroll
            for (int u = 0; u < 4; u++) { o[u] += bias[tx * 4 + u]; o[u + 4] += bias[64 + tx * 4 + u]; }
        }
        if (relu) {
#pragma unroll
            for (int u = 0; u < 8; u++) o[u] = fmaxf(o[u], 0.f);
        }
        *(float4*)(C + (size_t)row * ldc + tx * 4) = make_float4(o[0], o[1], o[2], o[3]);
        *(float4*)(C + (size_t)row * ldc + 64 + tx * 4) = make_float4(o[4], o[5], o[6], o[7]);
    }
}

__global__ void gemm128_kernel(const float* __restrict__ A, const float* __restrict__ B,
                               const float* __restrict__ bias, float* __restrict__ C,
                               int M, int K, int lda, int ldc, int relu) {
    gemm_tile(A, B, bias, C, M, K, lda, ldc, relu, blockIdx.x * 32);
}

// two independent 128x128 GEMMs (one per graph)
__global__ void gemm_b_kernel(const float* __restrict__ A, const float* __restrict__ B0,
                              const float* __restrict__ B1, float* __restrict__ C) {
    int g = blockIdx.y;
    gemm_tile(A + (size_t)g * NP * H, g ? B1 : B0, 0, C + (size_t)g * NP * H,
              NN, H, H, H, 0, blockIdx.x * 32);
}

// q/k projection: grid (188, 4 heads, 2 [q|k])
__global__ void qk_kernel(const float* __restrict__ xr, const float* __restrict__ xg,
                          const float* __restrict__ Wa, const float* __restrict__ ba,
                          float* __restrict__ q, float* __restrict__ k) {
    const float* A = blockIdx.z ? xg : xr;
    float* C = (blockIdx.z ? k : q) + (size_t)blockIdx.y * NP * H;
    gemm_tile(A, Wa + blockIdx.y * H * H, ba + blockIdx.y * H, C, NN, H, H, H, 0,
              blockIdx.x * 32);
}

// ---------------- flash attention, split-K (2 splits of 47 k-tiles) ----------------
__global__ void __launch_bounds__(128, 2)
flash_kernel(const float* __restrict__ qbuf, const float* __restrict__ kbuf,
             const float* __restrict__ vbuf, float* __restrict__ opart,
             float* __restrict__ mpart, float* __restrict__ lpart) {
    extern __shared__ __align__(16) float sm[];
    float* Qs = sm;                    // 64*132
    float* KVs = sm + 64 * 132;        // 64*132
    float* Ps = sm + 2 * 64 * 132;     // 64*68
    int tid = threadIdx.x;
    int tx = tid & 15, ty = tid >> 4;
    int qbase = blockIdx.x * 64;
    int head = blockIdx.y;
    int split = blockIdx.z;
    const float* Q = qbuf + (size_t)head * NP * H;
    const float* K = kbuf + (size_t)head * NP * H;

#pragma unroll
    for (int i = 0; i < 16; i++) {
        int idx = tid + 128 * i;
        int r = idx >> 5;
        int c4 = (idx & 31) << 2;
        *(float4*)(Qs + r * 132 + c4) = *(const float4*)(Q + (size_t)(qbase + r) * H + c4);
    }

    unsigned long long O2[8][4];
    float m[8], l[8];
#pragma unroll
    for (int i = 0; i < 8; i++) {
        m[i] = NEG_BIG; l[i] = 0.f;
#pragma unroll
        for (int u = 0; u < 4; u++) O2[i][u] = 0ull;
    }

    const int t0 = split * 47, t1 = t0 + 47;
    for (int kt = t0; kt < t1; kt++) {
        int kbase = kt * 64;
        __syncthreads();
#pragma unroll
        for (int i = 0; i < 16; i++) {
            int idx = tid + 128 * i;
            int r = idx >> 5;
            int c4 = (idx & 31) << 2;
            *(float4*)(KVs + r * 132 + c4) = *(const float4*)(K + (size_t)(kbase + r) * H + c4);
        }
        __syncthreads();

        unsigned long long S2[8][4];
#pragma unroll
        for (int i = 0; i < 8; i++)
#pragma unroll
            for (int j = 0; j < 4; j++) S2[i][j] = 0ull;
#pragma unroll 2
        for (int kk = 0; kk < 128; kk += 4) {
            ulonglong2 k0 = *(const ulonglong2*)(KVs + (tx + 0) * 132 + kk);
            ulonglong2 k1 = *(const ulonglong2*)(KVs + (tx + 16) * 132 + kk);
            ulonglong2 k2 = *(const ulonglong2*)(KVs + (tx + 32) * 132 + kk);
            ulonglong2 k3 = *(const ulonglong2*)(KVs + (tx + 48) * 132 + kk);
#pragma unroll
            for (int i = 0; i < 8; i++) {
                ulonglong2 qv = *(const ulonglong2*)(Qs + (ty * 8 + i) * 132 + kk);
                ffma2(S2[i][0], qv.x, k0.x); ffma2(S2[i][0], qv.y, k0.y);
                ffma2(S2[i][1], qv.x, k1.x); ffma2(S2[i][1], qv.y, k1.y);
                ffma2(S2[i][2], qv.x, k2.x); ffma2(S2[i][2], qv.y, k2.y);
                ffma2(S2[i][3], qv.x, k3.x); ffma2(S2[i][3], qv.y, k3.y);
            }
        }
        float S[8][4];
#pragma unroll
        for (int i = 0; i < 8; i++)
#pragma unroll
            for (int j = 0; j < 4; j++) {
                float2 f = unpk(S2[i][j]);
                S[i][j] = f.x + f.y;
            }
#pragma unroll
        for (int j = 0; j < 4; j++) {
            if (kbase + tx + 16 * j >= NN) {
#pragma unroll
                for (int i = 0; i < 8; i++) S[i][j] = NEG_BIG;
            }
        }
#pragma unroll
        for (int i = 0; i < 8; i++) {
            float mt = fmaxf(fmaxf(S[i][0], S[i][1]), fmaxf(S[i][2], S[i][3]));
            mt = fmaxf(mt, __shfl_xor_sync(0xffffffffu, mt, 1));
            mt = fmaxf(mt, __shfl_xor_sync(0xffffffffu, mt, 2));
            mt = fmaxf(mt, __shfl_xor_sync(0xffffffffu, mt, 4));
            mt = fmaxf(mt, __shfl_xor_sync(0xffffffffu, mt, 8));
            float mn = fmaxf(m[i], mt);
            float al = __expf(m[i] - mn);
            float p0 = __expf(S[i][0] - mn);
            float p1 = __expf(S[i][1] - mn);
            float p2 = __expf(S[i][2] - mn);
            float p3 = __expf(S[i][3] - mn);
            float rs = (p0 + p1) + (p2 + p3);
            rs += __shfl_xor_sync(0xffffffffu, rs, 1);
            rs += __shfl_xor_sync(0xffffffffu, rs, 2);
            rs += __shfl_xor_sync(0xffffffffu, rs, 4);
            rs += __shfl_xor_sync(0xffffffffu, rs, 8);
            l[i] = l[i] * al + rs;
            m[i] = mn;
            Ps[(ty * 8 + i) * 68 + tx + 0] = p0;
            Ps[(ty * 8 + i) * 68 + tx + 16] = p1;
            Ps[(ty * 8 + i) * 68 + tx + 32] = p2;
            Ps[(ty * 8 + i) * 68 + tx + 48] = p3;
            unsigned long long al2 = packdup(al);
#pragma unroll
            for (int u = 0; u < 4; u++) O2[i][u] = mul2(O2[i][u], al2);
        }
        __syncthreads();
#pragma unroll
        for (int i = 0; i < 16; i++) {
            int idx = tid + 128 * i;
            int r = idx >> 5;
            int c4 = (idx & 31) << 2;
            *(float4*)(KVs + r * 132 + c4) = *(const float4*)(vbuf + (size_t)(kbase + r) * H + c4);
        }
        __syncthreads();
#pragma unroll 4
        for (int c = 0; c < 64; c++) {
            ulonglong2 v0 = *(const ulonglong2*)(KVs + c * 132 + tx * 4);
            ulonglong2 v1 = *(const ulonglong2*)(KVs + c * 132 + 64 + tx * 4);
#pragma unroll
            for (int i = 0; i < 8; i++) {
                unsigned long long pp = packdup(Ps[(ty * 8 + i) * 68 + c]);
                ffma2(O2[i][0], pp, v0.x);
                ffma2(O2[i][1], pp, v0.y);
                ffma2(O2[i][2], pp, v1.x);
                ffma2(O2[i][3], pp, v1.y);
            }
        }
    }
    // write unnormalized partials
#pragma unroll
    for (int i = 0; i < 8; i++) {
        int row = qbase + ty * 8 + i;
        if (row >= NN) continue;
        size_t idx = (size_t)(split * 4 + head) * NP + row;
        if (tx == 0) { mpart[idx] = m[i]; lpart[idx] = l[i]; }
        float* dst = opart + idx * H;
        float2 a0 = unpk(O2[i][0]);
        float2 a1 = unpk(O2[i][1]);
        float2 a2 = unpk(O2[i][2]);
        float2 a3 = unpk(O2[i][3]);
        *(float4*)(dst + tx * 4) = make_float4(a0.x, a0.y, a1.x, a1.y);
        *(float4*)(dst + 64 + tx * 4) = make_float4(a2.x, a2.y, a3.x, a3.y);
    }
}

// merge the two splits -> hcat[:, 128 + head*128 ..]
__global__ void k_merge(const float* __restrict__ opart, const float* __restrict__ mpart,
                        const float* __restrict__ lpart, float* __restrict__ hcat) {
    int wrp = (blockIdx.x * blockDim.x + threadIdx.x) >> 5;
    int lane = threadIdx.x & 31;
    if (wrp >= NN * 4) return;
    int head = wrp / NN;
    int row = wrp - head * NN;
    size_t i0 = (size_t)(0 * 4 + head) * NP + row;
    size_t i1 = (size_t)(1 * 4 + head) * NP + row;
    float m0 = mpart[i0], m1 = mpart[i1];
    float l0 = lpart[i0], l1 = lpart[i1];
    float mm = fmaxf(m0, m1);
    float e0 = __expf(m0 - mm), e1 = __expf(m1 - mm);
    float inv = 1.f / (e0 * l0 + e1 * l1);
    float4 a = ((const float4*)(opart + i0 * H))[lane];
    float4 b = ((const float4*)(opart + i1 * H))[lane];
    float4 o;
    o.x = (e0 * a.x + e1 * b.x) * inv;
    o.y = (e0 * a.y + e1 * b.y) * inv;
    o.z = (e0 * a.z + e1 * b.z) * inv;
    o.w = (e0 * a.w + e1 * b.w) * inv;
    *(float4*)(hcat + (size_t)row * 640 + 128 + head * H + lane * 4) = o;
}

// final projection 128 -> 3
__global__ void k_wout(const float* __restrict__ h, const float* __restrict__ Wout,
                       const float* __restrict__ bout, float* __restrict__ out) {
    int n = blockIdx.x * blockDim.x + threadIdx.x;
    if (n >= NN) return;
    float a0 = bout[0], a1 = bout[1], a2 = bout[2];
    const float4* h4 = (const float4*)(h + (size_t)n * H);
#pragma unroll 8
    for (int k4 = 0; k4 < 32; k4++) {
        float4 v = h4[k4];
        int k = k4 * 4;
        a0 += v.x * Wout[(k + 0) * 3 + 0] + v.y * Wout[(k + 1) * 3 + 0] +
              v.z * Wout[(k + 2) * 3 + 0] + v.w * Wout[(k + 3) * 3 + 0];
        a1 += v.x * Wout[(k + 0) * 3 + 1] + v.y * Wout[(k + 1) * 3 + 1] +
              v.z * Wout[(k + 2) * 3 + 1] + v.w * Wout[(k + 3) * 3 + 1];
        a2 += v.x * Wout[(k + 0) * 3 + 2] + v.y * Wout[(k + 1) * 3 + 2] +
              v.z * Wout[(k + 2) * 3 + 2] + v.w * Wout[(k + 3) * 3 + 2];
    }
    out[n * 3 + 0] = a0;
    out[n * 3 + 1] = a1;
    out[n * 3 + 2] = a2;
}

// ---------------- host side ----------------
extern "C" void kernel_launch(void* const* d_in, const int* in_sizes, int n_in,
                              void* d_out, int out_size) {
    const float* x_resting = (const float*)d_in[0];
    const float* x_rigid   = (const float*)d_in[1];
    const int*   e_rest    = (const int*)d_in[2];
    const int*   e_rigid   = (const int*)d_in[3];
    const float* Wr0 = (const float*)d_in[4];
    const float* br0 = (const float*)d_in[5];
    const float* Wr  = (const float*)d_in[6];
    const float* br  = (const float*)d_in[7];
    const float* Wg0 = (const float*)d_in[8];
    const float* bg0 = (const float*)d_in[9];
    const float* Wg  = (const float*)d_in[10];
    const float* bg  = (const float*)d_in[11];
    const float* Wa  = (const float*)d_in[12];
    const float* ba  = (const float*)d_in[13];
    const float* Wd0 = (const float*)d_in[14];
    const float* bd0 = (const float*)d_in[15];
    const float* Wd  = (const float*)d_in[16];
    const float* bd  = (const float*)d_in[17];
    const float* Wout = (const float*)d_in[18];
    const float* bout = (const float*)d_in[19];
    float* out = (float*)d_out;

    void *p_cnt, *p_dinv, *p_ptr, *p_cur, *p_src, *p_nrm;
    void *p_hw, *p_ha, *p_xr, *p_xg, *p_q, *p_k, *p_hcat, *p_op, *p_mp, *p_lp;
    cudaGetSymbolAddress(&p_cnt, g_cnt);
    cudaGetSymbolAddress(&p_dinv, g_dinv);
    cudaGetSymbolAddress(&p_ptr, g_ptr);
    cudaGetSymbolAddress(&p_cur, g_cursor);
    cudaGetSymbolAddress(&p_src, g_src);
    cudaGetSymbolAddress(&p_nrm, g_nrm);
    cudaGetSymbolAddress(&p_hw, g_hw);
    cudaGetSymbolAddress(&p_ha, g_ha);
    cudaGetSymbolAddress(&p_xr, g_xr);
    cudaGetSymbolAddress(&p_xg, g_xg);
    cudaGetSymbolAddress(&p_q, g_q);
    cudaGetSymbolAddress(&p_k, g_k);
    cudaGetSymbolAddress(&p_hcat, g_hcat);
    cudaGetSymbolAddress(&p_op, g_opart);
    cudaGetSymbolAddress(&p_mp, g_mpart);
    cudaGetSymbolAddress(&p_lp, g_lpart);

    float* hw = (float*)p_hw;
    float* ha = (float*)p_ha;
    int* ptr = (int*)p_ptr;
    int* src = (int*)p_src;
    float* nrm = (float*)p_nrm;

    // zero cnt, and padded tails of xg / k (flash reads pad rows)
    cudaMemsetAsync(p_cnt, 0, 2 * NN * sizeof(int));
    cudaMemsetAsync(p_xg, 0, (size_t)NP * H * sizeof(float));
    cudaMemsetAsync(p_k, 0, (size_t)4 * NP * H * sizeof(float));

    // preproc (both graphs)
    {
        dim3 gc((EE + 255) / 256, 2);
        k_count_b<<<gc, 256>>>(e_rest, e_rigid, (int*)p_cnt);
        k_scan_b<<<2, 1024>>>((const int*)p_cnt, ptr, (int*)p_cur, (float*)p_dinv);
        dim3 gf((EE + NN + 255) / 256, 2);
        k_fill_b<<<gf, 256>>>(e_rest, e_rigid, (const float*)p_dinv, (int*)p_cur, src, nrm);
    }

    // encoders (both graphs, batched)
    {
        dim3 gl((NN + 1) / 2, 2);
        k_lin3_b<<<gl, 256>>>(x_resting, x_rigid, Wr0, Wg0, hw);
        dim3 gg((NN * 32 + 255) / 256, 2);
        dim3 gm(188, 2);
        k_gather_b<<<gg, 256>>>(hw, ptr, src, nrm, br0, bg0, ha, ha + (size_t)NP * H, 0);
        gemm_b_kernel<<<gm, 128>>>(ha, Wr, Wg, hw);
        k_gather_b<<<gg, 256>>>(hw, ptr, src, nrm, br, bg, ha, ha + (size_t)NP * H, 0);
        gemm_b_kernel<<<gm, 128>>>(ha, Wr + H * H, Wg + H * H, hw);
        k_gather_b<<<gg, 256>>>(hw, ptr, src, nrm, br + H, bg + H,
                                (float*)p_xr, (float*)p_xg, (float*)p_hcat);
    }

    // q/k projections for all 4 heads
    {
        dim3 grid(188, 4, 2);
        qk_kernel<<<grid, 128>>>((const float*)p_xr, (const float*)p_xg, Wa, ba,
                                 (float*)p_q, (float*)p_k);
    }

    // flash attention split-K + merge
    {
        int smem = (2 * 64 * 132 + 64 * 68) * (int)sizeof(float);  // 84992 B
        cudaFuncSetAttribute(flash_kernel, cudaFuncAttributeMaxDynamicSharedMemorySize, smem);
        dim3 grid(94, 4, 2);
        flash_kernel<<<grid, 128, smem>>>((const float*)p_q, (const float*)p_k,
                                          (const float*)p_xg, (float*)p_op,
                                          (float*)p_mp, (float*)p_lp);
        k_merge<<<(NN * 4 * 32 + 255) / 256, 256>>>((const float*)p_op, (const float*)p_mp,
                                                    (const float*)p_lp, (float*)p_hcat);
    }

    // decoder
    gemm128_kernel<<<188, 128>>>((const float*)p_hcat, Wd0, bd0, ha, NN, 5 * H, 5 * H, H, 1);
    gemm128_kernel<<<188, 128>>>(ha, Wd, bd, hw, NN, H, H, H, 1);
    gemm128_kernel<<<188, 128>>>(hw, Wd + H * H, bd + H, ha, NN, H, H, H, 1);
    k_wout<<<(NN + 255) / 256, 256>>>(ha, Wout, bout, out);
}